// round 2
// baseline (speedup 1.0000x reference)
#include <cuda_runtime.h>
#include <cuda_bf16.h>

#define NB 4
#define D0 64
#define C1 64
#define C2 128
#define DS 32
#define NCELL (NB*DS*DS*DS)   // 131072

// ---------------- scratch (device globals; no allocation allowed) ----------
__device__ float g_hds[NCELL*C1];   // downsampled h       33.5 MB
__device__ float g_xds[NCELL*C1];   // downsampled x*m     33.5 MB
__device__ float g_m2 [NCELL];      // mask2 as float
__device__ float g_t1 [NCELL*C2];   // after conv1         67 MB
__device__ float g_t2 [NCELL*C2];   // after norm2+silu    67 MB
__device__ int   g_mask_mode;       // 0=int32/float32 word, 2=byte

// ---------------- mask dtype detection -------------------------------------
__global__ void k_detect(const unsigned int* __restrict__ m, int nwords)
{
    if (threadIdx.x == 0 && blockIdx.x == 0) {
        int mode = 0;
        for (int i = 0; i < nwords; i++) {
            unsigned w = m[i];
            if (w == 0u) continue;
            if (w == 1u)               mode = 0;   // int32 0/1
            else if (w == 0x3F800000u) mode = 0;   // float32 1.0 (nonzero word works too)
            else                       mode = 2;   // packed bytes
            break;
        }
        g_mask_mode = mode;
    }
}

__device__ __forceinline__ bool mask_at(const void* m, long v, int mode)
{
    if (mode == 2) return ((const unsigned char*)m)[v] != 0;
    return ((const unsigned int*)m)[v] != 0u;
}

// ---------------- K1: LN1 + affine + SiLU + mask + 2x downsample (h and x) -
__global__ void k_ln_ds(const float* __restrict__ feats, const void* __restrict__ mask,
                        const float* __restrict__ gamma, const float* __restrict__ beta)
{
    const int c  = threadIdx.x;             // 64 channels
    const int dx = blockIdx.x, dy = blockIdx.y;
    const int b  = blockIdx.z >> 5, dz = blockIdx.z & 31;
    const int mode = g_mask_mode;

    __shared__ float sh1[2], sh2[2];

    const float g  = gamma[c];
    const float be = beta[c];
    float hsum = 0.f, xsum = 0.f;
    int cnt = 0;

    #pragma unroll
    for (int s = 0; s < 8; s++) {
        const int z = 2*dz + (s >> 2);
        const int y = 2*dy + ((s >> 1) & 1);
        const int x = 2*dx + (s & 1);
        const long v = (((long)b*D0 + z)*D0 + y)*D0 + x;
        const bool act = mask_at(mask, v, mode);
        const float xv = feats[v*C1 + c];

        float a = xv, q = xv*xv;
        #pragma unroll
        for (int o = 16; o > 0; o >>= 1) {
            a += __shfl_xor_sync(0xffffffffu, a, o);
            q += __shfl_xor_sync(0xffffffffu, q, o);
        }
        const int w = c >> 5;
        if ((c & 31) == 0) { sh1[w] = a; sh2[w] = q; }
        __syncthreads();
        const float sa = sh1[0] + sh1[1];
        const float sq = sh2[0] + sh2[1];
        __syncthreads();

        const float mu  = sa * (1.f/64.f);
        const float var = sq * (1.f/64.f) - mu*mu;
        const float ln  = (xv - mu) * rsqrtf(var + 1e-6f);
        const float hh  = ln * g + be;
        const float sil = hh / (1.f + __expf(-hh));
        if (act) { hsum += sil; xsum += xv; cnt++; }
    }

    const long cell = (((long)b*DS + dz)*DS + dy)*DS + dx;
    const float inv = 1.f / (float)max(cnt, 1);
    g_hds[cell*C1 + c] = hsum * inv;
    g_xds[cell*C1 + c] = xsum * inv;
    if (c == 0) g_m2[cell] = (cnt > 0) ? 1.f : 0.f;
}

// ---------------- conv: dense SAME 3x3x3 conv, masked output ----------------
// One block per (b, dz, dy) row: 32 voxels x COUT outputs. threadIdx.x = co.
template<int CIN, int COUT>
__global__ void __launch_bounds__(128, 2)
k_conv(const float* __restrict__ in, const float* __restrict__ wgt,
       const float* __restrict__ bias, const float* __restrict__ m2,
       float* __restrict__ out)
{
    extern __shared__ float smem[];
    float* s_in = smem;              // [34][CIN]
    float* s_w  = smem + 34*CIN;     // [CIN][COUT]

    const int co = threadIdx.x;      // COUT == 128 == blockDim.x
    const int dy = blockIdx.x, dz = blockIdx.y, b = blockIdx.z;

    float acc[32];
    #pragma unroll
    for (int w = 0; w < 32; w++) acc[w] = 0.f;

    for (int kd = 0; kd < 3; kd++) {
        const int z = dz + kd - 1;
        if ((unsigned)z >= DS) continue;
        for (int kh = 0; kh < 3; kh++) {
            const int y = dy + kh - 1;
            if ((unsigned)y >= DS) continue;

            __syncthreads();   // previous tap finished with s_in
            const float* rowbase = in + ((((long)b*DS + z)*DS + y)*DS) * CIN;
            for (int i = co; i < 34*CIN; i += 128) {
                const int p  = i / CIN;
                const int ci = i - p*CIN;
                const int wi = p - 1;
                s_in[i] = ((unsigned)wi < DS) ? rowbase[(long)wi*CIN + ci] : 0.f;
            }

            for (int kw = 0; kw < 3; kw++) {
                __syncthreads();  // protect s_w reuse + s_in visibility
                const float4* wsrc = (const float4*)(wgt + ((long)((kd*3 + kh)*3 + kw)) * CIN * COUT);
                float4* wdst = (float4*)s_w;
                #pragma unroll 4
                for (int i = co; i < CIN*COUT/4; i += 128) wdst[i] = wsrc[i];
                __syncthreads();

                #pragma unroll 2
                for (int ci = 0; ci < CIN; ci++) {
                    const float wv = s_w[ci*COUT + co];
                    const float* ip = s_in + kw*CIN + ci;
                    #pragma unroll
                    for (int w = 0; w < 32; w++)
                        acc[w] += ip[w*CIN] * wv;
                }
            }
        }
    }

    const long cellbase = (((long)b*DS + dz)*DS + dy)*DS;
    const float bv = bias[co];
    #pragma unroll 4
    for (int w = 0; w < 32; w++) {
        const float m = m2[cellbase + w];
        out[(cellbase + w)*COUT + co] = (acc[w] + bv) * m;
    }
}

// ---------------- K3: LN2 (no affine) + SiLU + mask -------------------------
__global__ void k_norm2(const float* __restrict__ t1, const float* __restrict__ m2,
                        float* __restrict__ t2)
{
    const int c  = threadIdx.x;      // 128
    const int dx = blockIdx.x, dy = blockIdx.y;
    const int b  = blockIdx.z >> 5, dz = blockIdx.z & 31;
    const long cell = (((long)b*DS + dz)*DS + dy)*DS + dx;

    __shared__ float sh1[4], sh2[4];

    const float xv = t1[cell*C2 + c];
    float a = xv, q = xv*xv;
    #pragma unroll
    for (int o = 16; o > 0; o >>= 1) {
        a += __shfl_xor_sync(0xffffffffu, a, o);
        q += __shfl_xor_sync(0xffffffffu, q, o);
    }
    const int w = c >> 5;
    if ((c & 31) == 0) { sh1[w] = a; sh2[w] = q; }
    __syncthreads();
    const float sa = sh1[0] + sh1[1] + sh1[2] + sh1[3];
    const float sq = sh2[0] + sh2[1] + sh2[2] + sh2[3];

    const float mu  = sa * (1.f/128.f);
    const float var = sq * (1.f/128.f) - mu*mu;
    const float ln  = (xv - mu) * rsqrtf(var + 1e-6f);
    const float sil = ln / (1.f + __expf(-ln));
    t2[cell*C2 + c] = sil * m2[cell];
}

// ---------------- K5: skip linear (64->128) + bias + mask, fused add --------
__global__ void __launch_bounds__(128)
k_skip(const float* __restrict__ xds, const float* __restrict__ wsk,
       const float* __restrict__ bsk, const float* __restrict__ m2,
       float* __restrict__ out)
{
    __shared__ float s_w[C1*C2];     // 32 KB
    __shared__ float s_x[32*C1];     // 8 KB

    const int co = threadIdx.x;
    const int dy = blockIdx.x, dz = blockIdx.y, b = blockIdx.z;
    const long cellbase = (((long)b*DS + dz)*DS + dy)*DS;

    {
        const float4* ws = (const float4*)wsk;
        float4* wd = (float4*)s_w;
        #pragma unroll 4
        for (int i = co; i < C1*C2/4; i += 128) wd[i] = ws[i];
        const float4* xs = (const float4*)(xds + cellbase*C1);
        float4* xd = (float4*)s_x;
        #pragma unroll
        for (int i = co; i < 32*C1/4; i += 128) xd[i] = xs[i];
    }
    __syncthreads();

    float acc[32];
    #pragma unroll
    for (int w = 0; w < 32; w++) acc[w] = 0.f;
    #pragma unroll 2
    for (int ci = 0; ci < C1; ci++) {
        const float wv = s_w[ci*C2 + co];
        #pragma unroll
        for (int w = 0; w < 32; w++)
            acc[w] += s_x[w*C1 + ci] * wv;
    }

    const float bv = bsk[co];
    #pragma unroll 4
    for (int w = 0; w < 32; w++) {
        const float m = m2[cellbase + w];
        const long i = (cellbase + w)*C2 + co;
        out[i] = (m != 0.f) ? (out[i] + acc[w] + bv) : 0.f;
    }
}

// ---------------- launch ----------------------------------------------------
extern "C" void kernel_launch(void* const* d_in, const int* in_sizes, int n_in,
                              void* d_out, int out_size)
{
    const float* feats = (const float*)d_in[0];
    const void*  mask  = d_in[1];
    const float* gamma1= (const float*)d_in[2];
    const float* beta1 = (const float*)d_in[3];
    const float* w1    = (const float*)d_in[4];
    const float* b1    = (const float*)d_in[5];
    const float* w2    = (const float*)d_in[6];
    const float* b2    = (const float*)d_in[7];
    const float* wsk   = (const float*)d_in[8];
    const float* bsk   = (const float*)d_in[9];
    float* out = (float*)d_out;

    float *p_hds, *p_xds, *p_m2, *p_t1, *p_t2;
    cudaGetSymbolAddress((void**)&p_hds, g_hds);
    cudaGetSymbolAddress((void**)&p_xds, g_xds);
    cudaGetSymbolAddress((void**)&p_m2,  g_m2);
    cudaGetSymbolAddress((void**)&p_t1,  g_t1);
    cudaGetSymbolAddress((void**)&p_t2,  g_t2);

    // Detect mask dtype (scan bound = element_count/4 words: safe for any width)
    k_detect<<<1, 32>>>((const unsigned int*)mask, in_sizes[1] / 4);

    // Stage A: LN1+SiLU+mask fused with 2x downsample of h and x*m
    dim3 gA(DS, DS, NB*DS);          // (dx, dy, b*32+dz)
    k_ln_ds<<<gA, C1>>>(feats, mask, gamma1, beta1);

    // conv1: 64 -> 128
    dim3 gC(DS, DS, NB);             // (dy, dz, b)
    size_t sm1 = (size_t)(34*C1 + C1*C2) * sizeof(float);    // ~41.5 KB
    k_conv<C1, C2><<<gC, 128, sm1>>>(p_hds, w1, b1, p_m2, p_t1);

    // norm2 + SiLU + mask
    k_norm2<<<gA, C2>>>(p_t1, p_m2, p_t2);

    // conv2: 128 -> 128 (needs >48KB dynamic smem)
    size_t sm2 = (size_t)(34*C2 + C2*C2) * sizeof(float);    // ~83 KB
    cudaFuncSetAttribute(k_conv<C2, C2>,
                         cudaFuncAttributeMaxDynamicSharedMemorySize, (int)sm2);
    k_conv<C2, C2><<<gC, 128, sm2>>>(p_t2, w2, b2, p_m2, out);

    // skip linear + fused add into out
    k_skip<<<gC, 128>>>(p_xds, wsk, bsk, p_m2, out);
}

// round 3
// speedup vs baseline: 1.0873x; 1.0873x over previous
#include <cuda_runtime.h>
#include <cuda_bf16.h>

#define NB 4
#define D0 64
#define C1 64
#define C2 128
#define DS 32
#define NCELL (NB*DS*DS*DS)   // 131072

// ---------------- scratch (device globals; no allocation allowed) ----------
__device__ float g_hds[NCELL*C1];   // downsampled h       33.5 MB
__device__ float g_xds[NCELL*C1];   // downsampled x*m     33.5 MB
__device__ float g_m2 [NCELL];      // mask2 as float
__device__ float g_t2 [NCELL*C2];   // after conv1+norm2+silu
__device__ int   g_mask_mode;       // 0=word, 2=byte

// ---------------- mask dtype detection -------------------------------------
__global__ void k_detect(const unsigned int* __restrict__ m, int nwords)
{
    if (threadIdx.x == 0 && blockIdx.x == 0) {
        int mode = 0;
        for (int i = 0; i < nwords; i++) {
            unsigned w = m[i];
            if (w == 0u) continue;
            if (w == 1u)               mode = 0;
            else if (w == 0x3F800000u) mode = 0;
            else                       mode = 2;
            break;
        }
        g_mask_mode = mode;
    }
}

__device__ __forceinline__ bool mask_at(const void* m, long v, int mode)
{
    if (mode == 2) return ((const unsigned char*)m)[v] != 0;
    return ((const unsigned int*)m)[v] != 0u;
}

// ---------------- f32x2 helpers ---------------------------------------------
__device__ __forceinline__ unsigned long long dup2(float x){
    unsigned long long r;
    asm("mov.b64 %0, {%1, %1};" : "=l"(r) : "f"(x));
    return r;
}
__device__ __forceinline__ void ffma2(unsigned long long& d, unsigned long long a, unsigned long long b){
    asm("fma.rn.f32x2 %0, %1, %2, %0;" : "+l"(d) : "l"(a), "l"(b));
}
__device__ __forceinline__ float lo32(unsigned long long v){ return __uint_as_float((unsigned)(v & 0xffffffffull)); }
__device__ __forceinline__ float hi32(unsigned long long v){ return __uint_as_float((unsigned)(v >> 32)); }

// ---------------- K1: LN1 + affine + SiLU + mask + 2x downsample (h and x) -
__global__ void k_ln_ds(const float* __restrict__ feats, const void* __restrict__ mask,
                        const float* __restrict__ gamma, const float* __restrict__ beta)
{
    const int c  = threadIdx.x;             // 64 channels
    const int dx = blockIdx.x, dy = blockIdx.y;
    const int b  = blockIdx.z >> 5, dz = blockIdx.z & 31;
    const int mode = g_mask_mode;

    __shared__ float sh1[2], sh2[2];

    const float g  = gamma[c];
    const float be = beta[c];
    float hsum = 0.f, xsum = 0.f;
    int cnt = 0;

    #pragma unroll
    for (int s = 0; s < 8; s++) {
        const int z = 2*dz + (s >> 2);
        const int y = 2*dy + ((s >> 1) & 1);
        const int x = 2*dx + (s & 1);
        const long v = (((long)b*D0 + z)*D0 + y)*D0 + x;
        const bool act = mask_at(mask, v, mode);
        const float xv = feats[v*C1 + c];

        float a = xv, q = xv*xv;
        #pragma unroll
        for (int o = 16; o > 0; o >>= 1) {
            a += __shfl_xor_sync(0xffffffffu, a, o);
            q += __shfl_xor_sync(0xffffffffu, q, o);
        }
        const int w = c >> 5;
        if ((c & 31) == 0) { sh1[w] = a; sh2[w] = q; }
        __syncthreads();
        const float sa = sh1[0] + sh1[1];
        const float sq = sh2[0] + sh2[1];
        __syncthreads();

        const float mu  = sa * (1.f/64.f);
        const float var = sq * (1.f/64.f) - mu*mu;
        const float ln  = (xv - mu) * rsqrtf(var + 1e-6f);
        const float hh  = ln * g + be;
        const float sil = hh / (1.f + __expf(-hh));
        if (act) { hsum += sil; xsum += xv; cnt++; }
    }

    const long cell = (((long)b*DS + dz)*DS + dy)*DS + dx;
    const float inv = 1.f / (float)max(cnt, 1);
    g_hds[cell*C1 + c] = hsum * inv;
    g_xds[cell*C1 + c] = xsum * inv;
    if (c == 0) g_m2[cell] = (cnt > 0) ? 1.f : 0.f;
}

// ---------------- conv: dense SAME 3x3x3 conv, masked output ----------------
// Block: (b, dz, 4 dy-rows) strip = 128 voxels x 128 cout.
// 512 threads: thread tile = 4 voxels (along x) x 8 cout (4 f32x2 co-pairs).
// FUSE_LN: apply LayerNorm(no affine)+SiLU+mask to the conv output (norm2).
template<int CIN, bool FUSE_LN>
__global__ void __launch_bounds__(512, 1)
k_conv(const float* __restrict__ in, const float* __restrict__ wgt,
       const float* __restrict__ bias, const float* __restrict__ m2,
       float* __restrict__ out)
{
    extern __shared__ float smem[];
    float* s_in = smem;                  // [6 rows][34 vox][CIN]
    float* s_w  = smem + 6*34*CIN;       // [CIN][128]

    const int tid = threadIdx.x;
    const int cg  = tid & 15;
    const int co0 = cg * 8;
    const int vg  = tid >> 4;            // 0..31
    const int r   = vg >> 3;             // 0..3  (row within strip)
    const int dx0 = (vg & 7) * 4;        // 0..28

    const int dy0 = blockIdx.x * 4;
    const int dz  = blockIdx.y;
    const int b   = blockIdx.z;

    unsigned long long acc[4][4];
    #pragma unroll
    for (int v = 0; v < 4; v++)
        #pragma unroll
        for (int p = 0; p < 4; p++) acc[v][p] = 0ull;

    for (int kd = 0; kd < 3; kd++) {
        const int z = dz + kd - 1;
        if ((unsigned)z >= DS) continue;
        __syncthreads();   // previous tap done with s_in
        // stage s_in: rows dy0-1 .. dy0+4, x -1..32, zero padded
        {
            const float* plane = in + (((long)b*DS + z)*DS)*DS*CIN;
            const int q  = CIN/4;
            const int nq = 6*34*q;
            for (int i = tid; i < nq; i += 512) {
                const int p   = i / q;
                const int ci4 = i - p*q;
                const int rr  = p / 34;
                const int vv  = p - rr*34;
                const int dy  = dy0 - 1 + rr;
                const int x   = vv - 1;
                float4 val = make_float4(0.f, 0.f, 0.f, 0.f);
                if ((unsigned)dy < DS && (unsigned)x < DS)
                    val = ((const float4*)(plane + ((long)dy*DS + x)*CIN))[ci4];
                ((float4*)s_in)[i] = val;
            }
        }
        for (int kh = 0; kh < 3; kh++) {
            for (int kw = 0; kw < 3; kw++) {
                __syncthreads();   // prev compute done with s_w; s_in visible
                {
                    const float4* wsrc = (const float4*)(wgt + (long)((kd*3 + kh)*3 + kw)*CIN*C2);
                    float4* wdst = (float4*)s_w;
                    #pragma unroll
                    for (int i = tid; i < CIN*C2/4; i += 512) wdst[i] = wsrc[i];
                }
                __syncthreads();

                const float* pin = s_in + ((r + kh)*34 + dx0 + kw)*CIN;
                const float* pw  = s_w + co0;
                #pragma unroll 2
                for (int ci = 0; ci < CIN; ci++) {
                    const unsigned long long w0 = *(const unsigned long long*)(pw + 0);
                    const unsigned long long w1 = *(const unsigned long long*)(pw + 2);
                    const unsigned long long w2 = *(const unsigned long long*)(pw + 4);
                    const unsigned long long w3 = *(const unsigned long long*)(pw + 6);
                    const unsigned long long a0 = dup2(pin[ci]);
                    const unsigned long long a1 = dup2(pin[CIN   + ci]);
                    const unsigned long long a2 = dup2(pin[2*CIN + ci]);
                    const unsigned long long a3 = dup2(pin[3*CIN + ci]);
                    ffma2(acc[0][0], a0, w0); ffma2(acc[0][1], a0, w1);
                    ffma2(acc[0][2], a0, w2); ffma2(acc[0][3], a0, w3);
                    ffma2(acc[1][0], a1, w0); ffma2(acc[1][1], a1, w1);
                    ffma2(acc[1][2], a1, w2); ffma2(acc[1][3], a1, w3);
                    ffma2(acc[2][0], a2, w0); ffma2(acc[2][1], a2, w1);
                    ffma2(acc[2][2], a2, w2); ffma2(acc[2][3], a2, w3);
                    ffma2(acc[3][0], a3, w0); ffma2(acc[3][1], a3, w1);
                    ffma2(acc[3][2], a3, w2); ffma2(acc[3][3], a3, w3);
                    pw += C2;
                }
            }
        }
    }

    // ------- epilogue -------
    const long cellbase = (((long)b*DS + dz)*DS + (dy0 + r))*DS + dx0;
    float bv[8];
    *(float4*)(bv)     = *(const float4*)(bias + co0);
    *(float4*)(bv + 4) = *(const float4*)(bias + co0 + 4);

    #pragma unroll
    for (int v = 0; v < 4; v++) {
        const float m = m2[cellbase + v];
        float t[8];
        #pragma unroll
        for (int p = 0; p < 4; p++) {
            t[2*p]   = (lo32(acc[v][p]) + bv[2*p])   * m;
            t[2*p+1] = (hi32(acc[v][p]) + bv[2*p+1]) * m;
        }
        if (FUSE_LN) {
            // a voxel's 128 channels live in 16 consecutive lanes (8 each)
            float s = 0.f, q = 0.f;
            #pragma unroll
            for (int c = 0; c < 8; c++) { s += t[c]; q += t[c]*t[c]; }
            #pragma unroll
            for (int o = 1; o < 16; o <<= 1) {
                s += __shfl_xor_sync(0xffffffffu, s, o);
                q += __shfl_xor_sync(0xffffffffu, q, o);
            }
            const float mu  = s * (1.f/128.f);
            const float var = q * (1.f/128.f) - mu*mu;
            const float rs  = rsqrtf(var + 1e-6f);
            #pragma unroll
            for (int c = 0; c < 8; c++) {
                const float ln = (t[c] - mu) * rs;
                t[c] = (ln / (1.f + __expf(-ln))) * m;
            }
        }
        float* po = out + (cellbase + v)*C2 + co0;
        *(float4*)(po)     = *(const float4*)(t);
        *(float4*)(po + 4) = *(const float4*)(t + 4);
    }
}

// ---------------- skip linear (64->128) + bias + mask, fused add ------------
__global__ void __launch_bounds__(128)
k_skip(const float* __restrict__ xds, const float* __restrict__ wsk,
       const float* __restrict__ bsk, const float* __restrict__ m2,
       float* __restrict__ out)
{
    __shared__ float s_w[C1*C2];     // 32 KB
    __shared__ float s_x[32*C1];     // 8 KB

    const int co = threadIdx.x;
    const int dy = blockIdx.x, dz = blockIdx.y, b = blockIdx.z;
    const long cellbase = (((long)b*DS + dz)*DS + dy)*DS;

    {
        const float4* ws = (const float4*)wsk;
        float4* wd = (float4*)s_w;
        #pragma unroll 4
        for (int i = co; i < C1*C2/4; i += 128) wd[i] = ws[i];
        const float4* xs = (const float4*)(xds + cellbase*C1);
        float4* xd = (float4*)s_x;
        #pragma unroll
        for (int i = co; i < 32*C1/4; i += 128) xd[i] = xs[i];
    }
    __syncthreads();

    float acc[32];
    #pragma unroll
    for (int w = 0; w < 32; w++) acc[w] = 0.f;
    #pragma unroll 2
    for (int ci = 0; ci < C1; ci++) {
        const float wv = s_w[ci*C2 + co];
        #pragma unroll
        for (int w = 0; w < 32; w++)
            acc[w] += s_x[w*C1 + ci] * wv;
    }

    const float bvv = bsk[co];
    #pragma unroll 4
    for (int w = 0; w < 32; w++) {
        const float m = m2[cellbase + w];
        const long i = (cellbase + w)*C2 + co;
        out[i] = (m != 0.f) ? (out[i] + acc[w] + bvv) : 0.f;
    }
}

// ---------------- launch ----------------------------------------------------
extern "C" void kernel_launch(void* const* d_in, const int* in_sizes, int n_in,
                              void* d_out, int out_size)
{
    const float* feats = (const float*)d_in[0];
    const void*  mask  = d_in[1];
    const float* gamma1= (const float*)d_in[2];
    const float* beta1 = (const float*)d_in[3];
    const float* w1    = (const float*)d_in[4];
    const float* b1    = (const float*)d_in[5];
    const float* w2    = (const float*)d_in[6];
    const float* b2    = (const float*)d_in[7];
    const float* wsk   = (const float*)d_in[8];
    const float* bsk   = (const float*)d_in[9];
    float* out = (float*)d_out;

    float *p_hds, *p_xds, *p_m2, *p_t2;
    cudaGetSymbolAddress((void**)&p_hds, g_hds);
    cudaGetSymbolAddress((void**)&p_xds, g_xds);
    cudaGetSymbolAddress((void**)&p_m2,  g_m2);
    cudaGetSymbolAddress((void**)&p_t2,  g_t2);

    k_detect<<<1, 32>>>((const unsigned int*)mask, in_sizes[1] / 4);

    // Stage A: LN1+SiLU+mask fused with 2x downsample of h and x*m
    dim3 gA(DS, DS, NB*DS);
    k_ln_ds<<<gA, C1>>>(feats, mask, gamma1, beta1);

    // conv1 (64->128) with fused norm2+SiLU+mask epilogue -> t2
    dim3 gC(8, DS, NB);   // (dy strip, dz, b)
    size_t sm1 = (size_t)(6*34*C1 + C1*C2) * sizeof(float);   // ~83 KB
    cudaFuncSetAttribute(k_conv<C1, true>,
                         cudaFuncAttributeMaxDynamicSharedMemorySize, (int)sm1);
    k_conv<C1, true><<<gC, 512, sm1>>>(p_hds, w1, b1, p_m2, p_t2);

    // conv2 (128->128) -> out
    size_t sm2 = (size_t)(6*34*C2 + C2*C2) * sizeof(float);   // ~166 KB
    cudaFuncSetAttribute(k_conv<C2, false>,
                         cudaFuncAttributeMaxDynamicSharedMemorySize, (int)sm2);
    k_conv<C2, false><<<gC, 512, sm2>>>(p_t2, w2, b2, p_m2, out);

    // skip linear + fused add into out
    dim3 gS(DS, DS, NB);
    k_skip<<<gS, 128>>>(p_xds, wsk, bsk, p_m2, out);
}

// round 4
// speedup vs baseline: 2.0073x; 1.8461x over previous
#include <cuda_runtime.h>
#include <cuda_bf16.h>

#define NB 4
#define D0 64
#define C1 64
#define C2 128
#define DS 32
#define NCELL (NB*DS*DS*DS)   // 131072
#define CISTRIDE 216          // 6 rows * 36 padded x
#define ROWPAD 36

// ---------------- scratch (device globals) ----------------------------------
__device__ float g_hds[NCELL*C1];
__device__ float g_xds[NCELL*C1];
__device__ float g_m2 [NCELL];
__device__ float g_t2 [NCELL*C2];
__device__ int   g_mask_mode;

// ---------------- mask dtype detection --------------------------------------
__global__ void k_detect(const unsigned int* __restrict__ m, int nwords)
{
    if (threadIdx.x == 0 && blockIdx.x == 0) {
        int mode = 0;
        for (int i = 0; i < nwords; i++) {
            unsigned w = m[i];
            if (w == 0u) continue;
            if (w == 1u)               mode = 0;
            else if (w == 0x3F800000u) mode = 0;
            else                       mode = 2;
            break;
        }
        g_mask_mode = mode;
    }
}
__device__ __forceinline__ bool mask_at(const void* m, long v, int mode)
{
    if (mode == 2) return ((const unsigned char*)m)[v] != 0;
    return ((const unsigned int*)m)[v] != 0u;
}

// ---------------- f32x2 helpers ----------------------------------------------
__device__ __forceinline__ unsigned long long dup2(float x){
    unsigned long long r;
    asm("mov.b64 %0, {%1, %1};" : "=l"(r) : "f"(x));
    return r;
}
__device__ __forceinline__ void ffma2(unsigned long long& d, unsigned long long a, unsigned long long b){
    asm("fma.rn.f32x2 %0, %1, %2, %0;" : "+l"(d) : "l"(a), "l"(b));
}
__device__ __forceinline__ float lo32(unsigned long long v){ return __uint_as_float((unsigned)(v & 0xffffffffull)); }
__device__ __forceinline__ float hi32(unsigned long long v){ return __uint_as_float((unsigned)(v >> 32)); }

// ---------------- K1: LN1+affine+SiLU+mask + 2x downsample -------------------
// One block (256 thr = 8 warps) per output cell; warp s handles subvoxel s.
__global__ void __launch_bounds__(256)
k_ln_ds(const float* __restrict__ feats, const void* __restrict__ mask,
        const float* __restrict__ gamma, const float* __restrict__ beta)
{
    const int bid = blockIdx.x;
    const int dx = bid & 31, dy = (bid >> 5) & 31, dz = (bid >> 10) & 31, b = bid >> 15;
    const int tid = threadIdx.x;
    const int s   = tid >> 5;          // subvoxel 0..7
    const int ln  = tid & 31;
    const int mode = g_mask_mode;

    __shared__ float sh_h[8*64];
    __shared__ float sh_x[8*64];
    __shared__ int   sh_c[8];

    const int z = 2*dz + (s >> 2);
    const int y = 2*dy + ((s >> 1) & 1);
    const int x = 2*dx + (s & 1);
    const long v = (((long)b*D0 + z)*D0 + y)*D0 + x;
    const bool act = mask_at(mask, v, mode);

    const float2 xv = *(const float2*)(feats + v*C1 + ln*2);
    float a = xv.x + xv.y;
    float q = xv.x*xv.x + xv.y*xv.y;
    #pragma unroll
    for (int o = 16; o > 0; o >>= 1) {
        a += __shfl_xor_sync(0xffffffffu, a, o);
        q += __shfl_xor_sync(0xffffffffu, q, o);
    }
    const float mu  = a * (1.f/64.f);
    const float var = q * (1.f/64.f) - mu*mu;
    const float rs  = rsqrtf(var + 1e-6f);

    const float2 g  = *(const float2*)(gamma + ln*2);
    const float2 be = *(const float2*)(beta  + ln*2);
    float h0 = (xv.x - mu)*rs*g.x + be.x;
    float h1 = (xv.y - mu)*rs*g.y + be.y;
    h0 = h0 / (1.f + __expf(-h0));
    h1 = h1 / (1.f + __expf(-h1));

    sh_h[s*64 + ln*2    ] = act ? h0 : 0.f;
    sh_h[s*64 + ln*2 + 1] = act ? h1 : 0.f;
    sh_x[s*64 + ln*2    ] = act ? xv.x : 0.f;
    sh_x[s*64 + ln*2 + 1] = act ? xv.y : 0.f;
    if (ln == 0) sh_c[s] = act ? 1 : 0;
    __syncthreads();

    if (tid < 64) {
        float hs = 0.f, xs = 0.f;
        int cnt = 0;
        #pragma unroll
        for (int k = 0; k < 8; k++) {
            hs += sh_h[k*64 + tid];
            xs += sh_x[k*64 + tid];
            cnt += sh_c[k];
        }
        const float inv = 1.f / (float)max(cnt, 1);
        g_hds[(long)bid*C1 + tid] = hs * inv;
        g_xds[(long)bid*C1 + tid] = xs * inv;
        if (tid == 0) g_m2[bid] = (cnt > 0) ? 1.f : 0.f;
    }
}

// ---------------- conv: dense SAME 3x3x3, masked output ----------------------
// Block: strip of 4 dy-rows x 32 x = 128 voxels, all 128 couts. 512 threads.
// Warp w: row r=w>>2, x0=(w&3)*8 (8 voxels); lane: co0=lane*4.
// s_in transposed [ci][6 rows][36 x] -> input loads warp-broadcast.
// Weights staged per (kd,kh) in 32-ci chunks, all 3 kw taps together.
template<int CIN, bool FUSE_LN>
__global__ void __launch_bounds__(512, 1)
k_conv(const float* __restrict__ in, const float* __restrict__ wgt,
       const float* __restrict__ bias, const float* __restrict__ m2,
       float* __restrict__ out)
{
    extern __shared__ float smem[];
    float* s_in = smem;                    // [CIN][6][36]
    float* s_w  = smem + CIN*CISTRIDE;     // [3 kw][32 ci][128 co]

    const int tid  = threadIdx.x;
    const int lane = tid & 31;
    const int w    = tid >> 5;             // warp 0..15
    const int co0  = lane * 4;
    const int r    = w >> 2;               // row in strip
    const int x0   = (w & 3) * 8;

    const int dy0 = blockIdx.x * 4;
    const int dz  = blockIdx.y;
    const int b   = blockIdx.z;

    // zero-fill s_in once (margins stay zero; interior overwritten per kd)
    {
        float4* p = (float4*)s_in;
        const int n4 = CIN*CISTRIDE/4;
        for (int i = tid; i < n4; i += 512) p[i] = make_float4(0.f,0.f,0.f,0.f);
    }

    unsigned long long acc[8][2];
    #pragma unroll
    for (int vv = 0; vv < 8; vv++) { acc[vv][0] = 0ull; acc[vv][1] = 0ull; }

    const float4* wgt4 = (const float4*)wgt;

    for (int kd = 0; kd < 3; kd++) {
        const int z = dz + kd - 1;
        if ((unsigned)z >= DS) continue;
        __syncthreads();   // previous compute done with s_in
        // stage s_in transposed: rows dy0-1..dy0+4
        {
            const float* plane = in + (((long)b*DS + z)*DS)*DS*CIN;
            const int total = 6*DS*CIN;
            for (int idx = tid; idx < total; idx += 512) {
                const int ridx = idx / (DS*CIN);
                const int rem  = idx - ridx*DS*CIN;
                const int xx   = rem / CIN;
                const int ci   = rem - xx*CIN;
                const int dyy  = dy0 - 1 + ridx;
                if ((unsigned)dyy < DS)
                    s_in[ci*CISTRIDE + ridx*ROWPAD + xx + 1] =
                        plane[((long)dyy*DS + xx)*CIN + ci];
            }
        }
        for (int kh = 0; kh < 3; kh++) {
            const float* inrow = s_in + (r + kh)*ROWPAD + x0;
            for (int ch = 0; ch < CIN/32; ch++) {
                __syncthreads();   // prev compute done with s_w (+ s_in visible)
                {
                    const int tapbase = (kd*3 + kh)*3;
                    #pragma unroll
                    for (int j = 0; j < 6; j++) {
                        const int flat = tid + j*512;       // float4 units, < 3072
                        const int kw   = flat >> 10;
                        const int rem  = flat & 1023;
                        const int ci   = rem >> 5;
                        const int co4  = rem & 31;
                        ((float4*)s_w)[flat] =
                            wgt4[((long)(tapbase + kw)*CIN + ch*32 + ci)*32 + co4];
                    }
                }
                __syncthreads();

                #pragma unroll 2
                for (int cil = 0; cil < 32; cil++) {
                    const int ci = ch*32 + cil;
                    const float* ip = inrow + ci*CISTRIDE;
                    float f[10];
                    *(float4*)(f)     = *(const float4*)(ip);
                    *(float4*)(f + 4) = *(const float4*)(ip + 4);
                    *(float2*)(f + 8) = *(const float2*)(ip + 8);
                    unsigned long long d[10];
                    #pragma unroll
                    for (int i = 0; i < 10; i++) d[i] = dup2(f[i]);
                    const ulonglong2 w0 = *(const ulonglong2*)(s_w + (0*32 + cil)*C2 + co0);
                    const ulonglong2 w1 = *(const ulonglong2*)(s_w + (1*32 + cil)*C2 + co0);
                    const ulonglong2 w2 = *(const ulonglong2*)(s_w + (2*32 + cil)*C2 + co0);
                    #pragma unroll
                    for (int vv = 0; vv < 8; vv++) {
                        ffma2(acc[vv][0], d[vv    ], w0.x); ffma2(acc[vv][1], d[vv    ], w0.y);
                        ffma2(acc[vv][0], d[vv + 1], w1.x); ffma2(acc[vv][1], d[vv + 1], w1.y);
                        ffma2(acc[vv][0], d[vv + 2], w2.x); ffma2(acc[vv][1], d[vv + 2], w2.y);
                    }
                }
            }
        }
    }

    // ------- epilogue -------
    const float4 bv = *(const float4*)(bias + co0);
    const long rowcell = (((long)b*DS + dz)*DS + (dy0 + r))*DS + x0;

    #pragma unroll
    for (int vv = 0; vv < 8; vv++) {
        const float m = m2[rowcell + vv];
        float t[4];
        t[0] = (lo32(acc[vv][0]) + bv.x) * m;
        t[1] = (hi32(acc[vv][0]) + bv.y) * m;
        t[2] = (lo32(acc[vv][1]) + bv.z) * m;
        t[3] = (hi32(acc[vv][1]) + bv.w) * m;
        if (FUSE_LN) {
            // voxel's 128 channels spread over the 32 lanes (4 each)
            float sA = t[0]+t[1]+t[2]+t[3];
            float qA = t[0]*t[0]+t[1]*t[1]+t[2]*t[2]+t[3]*t[3];
            #pragma unroll
            for (int o = 16; o > 0; o >>= 1) {
                sA += __shfl_xor_sync(0xffffffffu, sA, o);
                qA += __shfl_xor_sync(0xffffffffu, qA, o);
            }
            const float mu  = sA * (1.f/128.f);
            const float var = qA * (1.f/128.f) - mu*mu;
            const float rs  = rsqrtf(var + 1e-6f);
            #pragma unroll
            for (int c = 0; c < 4; c++) {
                const float lnv = (t[c] - mu) * rs;
                t[c] = (lnv / (1.f + __expf(-lnv))) * m;
            }
        }
        *(float4*)(out + (rowcell + vv)*C2 + co0) = *(const float4*)(t);
    }
}

// ---------------- skip linear (64->128) + bias + mask, fused add -------------
__global__ void __launch_bounds__(128)
k_skip(const float* __restrict__ xds, const float* __restrict__ wsk,
       const float* __restrict__ bsk, const float* __restrict__ m2,
       float* __restrict__ out)
{
    __shared__ float s_w[C1*C2];
    __shared__ float s_x[32*C1];

    const int co = threadIdx.x;
    const int dy = blockIdx.x, dz = blockIdx.y, b = blockIdx.z;
    const long cellbase = (((long)b*DS + dz)*DS + dy)*DS;

    {
        const float4* ws = (const float4*)wsk;
        float4* wd = (float4*)s_w;
        #pragma unroll 4
        for (int i = co; i < C1*C2/4; i += 128) wd[i] = ws[i];
        const float4* xs = (const float4*)(xds + cellbase*C1);
        float4* xd = (float4*)s_x;
        #pragma unroll
        for (int i = co; i < 32*C1/4; i += 128) xd[i] = xs[i];
    }
    __syncthreads();

    float acc[32];
    #pragma unroll
    for (int ww = 0; ww < 32; ww++) acc[ww] = 0.f;
    #pragma unroll 2
    for (int ci = 0; ci < C1; ci++) {
        const float wv = s_w[ci*C2 + co];
        #pragma unroll
        for (int ww = 0; ww < 32; ww++)
            acc[ww] += s_x[ww*C1 + ci] * wv;
    }

    const float bvv = bsk[co];
    #pragma unroll 4
    for (int ww = 0; ww < 32; ww++) {
        const float m = m2[cellbase + ww];
        const long i = (cellbase + ww)*C2 + co;
        out[i] = (m != 0.f) ? (out[i] + acc[ww] + bvv) : 0.f;
    }
}

// ---------------- launch ------------------------------------------------------
extern "C" void kernel_launch(void* const* d_in, const int* in_sizes, int n_in,
                              void* d_out, int out_size)
{
    const float* feats = (const float*)d_in[0];
    const void*  mask  = d_in[1];
    const float* gamma1= (const float*)d_in[2];
    const float* beta1 = (const float*)d_in[3];
    const float* w1    = (const float*)d_in[4];
    const float* b1    = (const float*)d_in[5];
    const float* w2    = (const float*)d_in[6];
    const float* b2    = (const float*)d_in[7];
    const float* wsk   = (const float*)d_in[8];
    const float* bsk   = (const float*)d_in[9];
    float* out = (float*)d_out;

    float *p_hds, *p_xds, *p_m2, *p_t2;
    cudaGetSymbolAddress((void**)&p_hds, g_hds);
    cudaGetSymbolAddress((void**)&p_xds, g_xds);
    cudaGetSymbolAddress((void**)&p_m2,  g_m2);
    cudaGetSymbolAddress((void**)&p_t2,  g_t2);

    k_detect<<<1, 32>>>((const unsigned int*)mask, in_sizes[1] / 4);

    k_ln_ds<<<NCELL, 256>>>(feats, mask, gamma1, beta1);

    dim3 gC(8, DS, NB);   // (dy strip, dz, b)
    size_t sm1 = (size_t)(C1*CISTRIDE + 3*32*C2) * sizeof(float);   // ~104 KB
    cudaFuncSetAttribute(k_conv<C1, true>,
                         cudaFuncAttributeMaxDynamicSharedMemorySize, (int)sm1);
    k_conv<C1, true><<<gC, 512, sm1>>>(p_hds, w1, b1, p_m2, p_t2);

    size_t sm2 = (size_t)(C2*CISTRIDE + 3*32*C2) * sizeof(float);   // ~156 KB
    cudaFuncSetAttribute(k_conv<C2, false>,
                         cudaFuncAttributeMaxDynamicSharedMemorySize, (int)sm2);
    k_conv<C2, false><<<gC, 512, sm2>>>(p_t2, w2, b2, p_m2, out);

    dim3 gS(DS, DS, NB);
    k_skip<<<gS, 128>>>(p_xds, wsk, bsk, p_m2, out);
}

// round 5
// speedup vs baseline: 2.0692x; 1.0308x over previous
#include <cuda_runtime.h>
#include <cuda_bf16.h>

#define NB 4
#define D0 64
#define C1 64
#define C2 128
#define DS 32
#define NCELL (NB*DS*DS*DS)   // 131072
#define CISTRIDE 216          // 6 rows * 36 padded x
#define ROWPAD 36
#define WCHUNK (3*32*C2)      // floats per weight stage (3 kw, 32 ci, 128 co)

// ---------------- scratch (device globals) ----------------------------------
__device__ float g_hds[NCELL*C1];
__device__ float g_xds[NCELL*C1];
__device__ float g_m2 [NCELL];
__device__ float g_t2 [NCELL*C2];
__device__ int   g_mask_mode;

// ---------------- mask dtype detection --------------------------------------
__global__ void k_detect(const unsigned int* __restrict__ m, int nwords)
{
    if (threadIdx.x == 0 && blockIdx.x == 0) {
        int mode = 0;
        for (int i = 0; i < nwords; i++) {
            unsigned w = m[i];
            if (w == 0u) continue;
            if (w == 1u)               mode = 0;
            else if (w == 0x3F800000u) mode = 0;
            else                       mode = 2;
            break;
        }
        g_mask_mode = mode;
    }
}
__device__ __forceinline__ bool mask_at(const void* m, long v, int mode)
{
    if (mode == 2) return ((const unsigned char*)m)[v] != 0;
    return ((const unsigned int*)m)[v] != 0u;
}

// ---------------- f32x2 / async helpers --------------------------------------
__device__ __forceinline__ unsigned long long dup2(float x){
    unsigned long long r;
    asm("mov.b64 %0, {%1, %1};" : "=l"(r) : "f"(x));
    return r;
}
__device__ __forceinline__ void ffma2(unsigned long long& d, unsigned long long a, unsigned long long b){
    asm("fma.rn.f32x2 %0, %1, %2, %0;" : "+l"(d) : "l"(a), "l"(b));
}
__device__ __forceinline__ float lo32(unsigned long long v){ return __uint_as_float((unsigned)(v & 0xffffffffull)); }
__device__ __forceinline__ float hi32(unsigned long long v){ return __uint_as_float((unsigned)(v >> 32)); }

__device__ __forceinline__ void cpa16(float* smem_dst, const float4* gsrc){
    unsigned s = (unsigned)__cvta_generic_to_shared(smem_dst);
    asm volatile("cp.async.cg.shared.global [%0], [%1], 16;" :: "r"(s), "l"(gsrc));
}
__device__ __forceinline__ void cpa_commit(){ asm volatile("cp.async.commit_group;"); }
__device__ __forceinline__ void cpa_wait0(){ asm volatile("cp.async.wait_group 0;"); }

// ---------------- K1: LN1+affine+SiLU+mask + 2x downsample -------------------
__global__ void __launch_bounds__(256)
k_ln_ds(const float* __restrict__ feats, const void* __restrict__ mask,
        const float* __restrict__ gamma, const float* __restrict__ beta)
{
    const int bid = blockIdx.x;
    const int dx = bid & 31, dy = (bid >> 5) & 31, dz = (bid >> 10) & 31, b = bid >> 15;
    const int tid = threadIdx.x;
    const int s   = tid >> 5;
    const int ln  = tid & 31;
    const int mode = g_mask_mode;

    __shared__ float sh_h[8*64];
    __shared__ float sh_x[8*64];
    __shared__ int   sh_c[8];

    const int z = 2*dz + (s >> 2);
    const int y = 2*dy + ((s >> 1) & 1);
    const int x = 2*dx + (s & 1);
    const long v = (((long)b*D0 + z)*D0 + y)*D0 + x;
    const bool act = mask_at(mask, v, mode);

    const float2 xv = *(const float2*)(feats + v*C1 + ln*2);
    float a = xv.x + xv.y;
    float q = xv.x*xv.x + xv.y*xv.y;
    #pragma unroll
    for (int o = 16; o > 0; o >>= 1) {
        a += __shfl_xor_sync(0xffffffffu, a, o);
        q += __shfl_xor_sync(0xffffffffu, q, o);
    }
    const float mu  = a * (1.f/64.f);
    const float var = q * (1.f/64.f) - mu*mu;
    const float rs  = rsqrtf(var + 1e-6f);

    const float2 g  = *(const float2*)(gamma + ln*2);
    const float2 be = *(const float2*)(beta  + ln*2);
    float h0 = (xv.x - mu)*rs*g.x + be.x;
    float h1 = (xv.y - mu)*rs*g.y + be.y;
    h0 = h0 / (1.f + __expf(-h0));
    h1 = h1 / (1.f + __expf(-h1));

    sh_h[s*64 + ln*2    ] = act ? h0 : 0.f;
    sh_h[s*64 + ln*2 + 1] = act ? h1 : 0.f;
    sh_x[s*64 + ln*2    ] = act ? xv.x : 0.f;
    sh_x[s*64 + ln*2 + 1] = act ? xv.y : 0.f;
    if (ln == 0) sh_c[s] = act ? 1 : 0;
    __syncthreads();

    if (tid < 64) {
        float hs = 0.f, xs = 0.f;
        int cnt = 0;
        #pragma unroll
        for (int k = 0; k < 8; k++) {
            hs += sh_h[k*64 + tid];
            xs += sh_x[k*64 + tid];
            cnt += sh_c[k];
        }
        const float inv = 1.f / (float)max(cnt, 1);
        g_hds[(long)bid*C1 + tid] = hs * inv;
        g_xds[(long)bid*C1 + tid] = xs * inv;
        if (tid == 0) g_m2[bid] = (cnt > 0) ? 1.f : 0.f;
    }
}

// ---------------- conv: dense SAME 3x3x3, masked output ----------------------
// Block: 4 dy-rows x 32 x = 128 voxels, all 128 couts. 512 threads.
// Warp w: row r=w>>2, x0=(w&3)*8; lane co0=lane*4.
// Weights double-buffered via cp.async (one barrier per 32-ci stage).
template<int CIN, bool FUSE_LN>
__global__ void __launch_bounds__(512, 1)
k_conv(const float* __restrict__ in, const float* __restrict__ wgt,
       const float* __restrict__ bias, const float* __restrict__ m2,
       float* __restrict__ out)
{
    extern __shared__ float smem[];
    float* s_in = smem;                       // [CIN][6][36]
    float* s_w  = smem + CIN*CISTRIDE;        // 2 x [3 kw][32 ci][128 co]

    const int tid  = threadIdx.x;
    const int lane = tid & 31;
    const int w    = tid >> 5;
    const int co0  = lane * 4;
    const int r    = w >> 2;
    const int x0   = (w & 3) * 8;

    const int dy0 = blockIdx.x * 4;
    const int dz  = blockIdx.y;
    const int b   = blockIdx.z;

    const int kdlo = (dz == 0)    ? 1 : 0;
    const int kdhi = (dz == DS-1) ? 1 : 2;
    const int NCH  = CIN / 32;
    const int nstage = (kdhi - kdlo + 1) * 3 * NCH;

    // zero-fill s_in margins (once)
    {
        float4* p = (float4*)s_in;
        const int n4 = CIN*CISTRIDE/4;
        for (int i = tid; i < n4; i += 512) p[i] = make_float4(0.f,0.f,0.f,0.f);
    }

    unsigned long long acc[8][2];
    #pragma unroll
    for (int vv = 0; vv < 8; vv++) { acc[vv][0] = 0ull; acc[vv][1] = 0ull; }

    const float4* wgt4 = (const float4*)wgt;

    // ---- weight prefetch state: next stage to fetch ----
    int nkd = kdlo, nkh = 0, nch = 0, nfetched = 0, si = 0;

    // prefetch helper (6 float4 per thread per stage)
    auto prefetch = [&](int bufpar){
        float* dst = s_w + bufpar * WCHUNK;
        const int tapbase = (nkd*3 + nkh)*3;
        #pragma unroll
        for (int j = 0; j < 6; j++) {
            const int flat = tid + j*512;        // float4 idx within chunk
            const int kw   = flat >> 10;
            const int rem  = flat & 1023;
            const int ci   = rem >> 5;
            const int co4  = rem & 31;
            cpa16(dst + flat*4,
                  &wgt4[((long)(tapbase + kw)*CIN + nch*32 + ci)*32 + co4]);
        }
        cpa_commit();
        nfetched++;
        nch++;
        if (nch == NCH) { nch = 0; nkh++; if (nkh == 3) { nkh = 0; nkd++; } }
    };

    prefetch(0);   // stage 0 -> buffer 0

    for (int kd = kdlo; kd <= kdhi; kd++) {
        const int z = dz + kd - 1;
        __syncthreads();   // previous kd's compute done with s_in
        // stage s_in transposed (overlaps with in-flight weight copy)
        {
            const float* plane = in + (((long)b*DS + z)*DS)*DS*CIN;
            const int total = 6*DS*CIN;
            for (int idx = tid; idx < total; idx += 512) {
                const int ridx = idx / (DS*CIN);
                const int rem  = idx - ridx*DS*CIN;
                const int xx   = rem / CIN;
                const int ci   = rem - xx*CIN;
                const int dyy  = dy0 - 1 + ridx;
                if ((unsigned)dyy < DS)
                    s_in[ci*CISTRIDE + ridx*ROWPAD + xx + 1] =
                        plane[((long)dyy*DS + xx)*CIN + ci];
            }
        }
        for (int kh = 0; kh < 3; kh++) {
            const float* inrow = s_in + (r + kh)*ROWPAD + x0;
            for (int ch = 0; ch < NCH; ch++) {
                cpa_wait0();        // own copies of stage si done
                __syncthreads();    // all copies visible; all warps past compute si-1
                if (nfetched < nstage) prefetch((si + 1) & 1);

                const float* wbuf = s_w + (si & 1) * WCHUNK;
                #pragma unroll 2
                for (int cil = 0; cil < 32; cil++) {
                    const int ci = ch*32 + cil;
                    const float* ip = inrow + ci*CISTRIDE;
                    float f[10];
                    *(float4*)(f)     = *(const float4*)(ip);
                    *(float4*)(f + 4) = *(const float4*)(ip + 4);
                    *(float2*)(f + 8) = *(const float2*)(ip + 8);
                    unsigned long long d[10];
                    #pragma unroll
                    for (int i = 0; i < 10; i++) d[i] = dup2(f[i]);
                    const ulonglong2 w0 = *(const ulonglong2*)(wbuf + (0*32 + cil)*C2 + co0);
                    const ulonglong2 w1 = *(const ulonglong2*)(wbuf + (1*32 + cil)*C2 + co0);
                    const ulonglong2 w2 = *(const ulonglong2*)(wbuf + (2*32 + cil)*C2 + co0);
                    #pragma unroll
                    for (int vv = 0; vv < 8; vv++) {
                        ffma2(acc[vv][0], d[vv    ], w0.x); ffma2(acc[vv][1], d[vv    ], w0.y);
                        ffma2(acc[vv][0], d[vv + 1], w1.x); ffma2(acc[vv][1], d[vv + 1], w1.y);
                        ffma2(acc[vv][0], d[vv + 2], w2.x); ffma2(acc[vv][1], d[vv + 2], w2.y);
                    }
                }
                si++;
            }
        }
    }

    // ------- epilogue -------
    const float4 bv = *(const float4*)(bias + co0);
    const long rowcell = (((long)b*DS + dz)*DS + (dy0 + r))*DS + x0;

    #pragma unroll
    for (int vv = 0; vv < 8; vv++) {
        const float m = m2[rowcell + vv];
        float t[4];
        t[0] = (lo32(acc[vv][0]) + bv.x) * m;
        t[1] = (hi32(acc[vv][0]) + bv.y) * m;
        t[2] = (lo32(acc[vv][1]) + bv.z) * m;
        t[3] = (hi32(acc[vv][1]) + bv.w) * m;
        if (FUSE_LN) {
            float sA = t[0]+t[1]+t[2]+t[3];
            float qA = t[0]*t[0]+t[1]*t[1]+t[2]*t[2]+t[3]*t[3];
            #pragma unroll
            for (int o = 16; o > 0; o >>= 1) {
                sA += __shfl_xor_sync(0xffffffffu, sA, o);
                qA += __shfl_xor_sync(0xffffffffu, qA, o);
            }
            const float mu  = sA * (1.f/128.f);
            const float var = qA * (1.f/128.f) - mu*mu;
            const float rs  = rsqrtf(var + 1e-6f);
            #pragma unroll
            for (int c = 0; c < 4; c++) {
                const float lnv = (t[c] - mu) * rs;
                t[c] = (lnv / (1.f + __expf(-lnv))) * m;
            }
        }
        *(float4*)(out + (rowcell + vv)*C2 + co0) = *(const float4*)(t);
    }
}

// ---------------- skip linear (64->128) + bias + mask, fused add -------------
__global__ void __launch_bounds__(128)
k_skip(const float* __restrict__ xds, const float* __restrict__ wsk,
       const float* __restrict__ bsk, const float* __restrict__ m2,
       float* __restrict__ out)
{
    __shared__ float s_w[C1*C2];
    __shared__ float s_x[32*C1];

    const int co = threadIdx.x;
    const int dy = blockIdx.x, dz = blockIdx.y, b = blockIdx.z;
    const long cellbase = (((long)b*DS + dz)*DS + dy)*DS;

    {
        const float4* ws = (const float4*)wsk;
        float4* wd = (float4*)s_w;
        #pragma unroll 4
        for (int i = co; i < C1*C2/4; i += 128) wd[i] = ws[i];
        const float4* xs = (const float4*)(xds + cellbase*C1);
        float4* xd = (float4*)s_x;
        #pragma unroll
        for (int i = co; i < 32*C1/4; i += 128) xd[i] = xs[i];
    }
    __syncthreads();

    float acc[32];
    #pragma unroll
    for (int ww = 0; ww < 32; ww++) acc[ww] = 0.f;
    #pragma unroll 2
    for (int ci = 0; ci < C1; ci++) {
        const float wv = s_w[ci*C2 + co];
        #pragma unroll
        for (int ww = 0; ww < 32; ww++)
            acc[ww] += s_x[ww*C1 + ci] * wv;
    }

    const float bvv = bsk[co];
    #pragma unroll 4
    for (int ww = 0; ww < 32; ww++) {
        const float m = m2[cellbase + ww];
        const long i = (cellbase + ww)*C2 + co;
        out[i] = (m != 0.f) ? (out[i] + acc[ww] + bvv) : 0.f;
    }
}

// ---------------- launch ------------------------------------------------------
extern "C" void kernel_launch(void* const* d_in, const int* in_sizes, int n_in,
                              void* d_out, int out_size)
{
    const float* feats = (const float*)d_in[0];
    const void*  mask  = d_in[1];
    const float* gamma1= (const float*)d_in[2];
    const float* beta1 = (const float*)d_in[3];
    const float* w1    = (const float*)d_in[4];
    const float* b1    = (const float*)d_in[5];
    const float* w2    = (const float*)d_in[6];
    const float* b2    = (const float*)d_in[7];
    const float* wsk   = (const float*)d_in[8];
    const float* bsk   = (const float*)d_in[9];
    float* out = (float*)d_out;

    float *p_hds, *p_xds, *p_m2, *p_t2;
    cudaGetSymbolAddress((void**)&p_hds, g_hds);
    cudaGetSymbolAddress((void**)&p_xds, g_xds);
    cudaGetSymbolAddress((void**)&p_m2,  g_m2);
    cudaGetSymbolAddress((void**)&p_t2,  g_t2);

    k_detect<<<1, 32>>>((const unsigned int*)mask, in_sizes[1] / 4);

    k_ln_ds<<<NCELL, 256>>>(feats, mask, gamma1, beta1);

    dim3 gC(8, DS, NB);   // (dy strip, dz, b)
    size_t sm1 = (size_t)(C1*CISTRIDE + 2*WCHUNK) * sizeof(float);   // ~151 KB
    cudaFuncSetAttribute(k_conv<C1, true>,
                         cudaFuncAttributeMaxDynamicSharedMemorySize, (int)sm1);
    k_conv<C1, true><<<gC, 512, sm1>>>(p_hds, w1, b1, p_m2, p_t2);

    size_t sm2 = (size_t)(C2*CISTRIDE + 2*WCHUNK) * sizeof(float);   // ~207 KB
    cudaFuncSetAttribute(k_conv<C2, false>,
                         cudaFuncAttributeMaxDynamicSharedMemorySize, (int)sm2);
    k_conv<C2, false><<<gC, 512, sm2>>>(p_t2, w2, b2, p_m2, out);

    dim3 gS(DS, DS, NB);
    k_skip<<<gS, 128>>>(p_xds, wsk, bsk, p_m2, out);
}